// round 10
// baseline (speedup 1.0000x reference)
#include <cuda_runtime.h>
#include <cstdint>
#include <cstddef>

// Problem dims: B=32 N=1024 D=512 H=8 ; BN = 32768
#define CB 32
#define CN 1024
#define CD 512
#define CH 8

// ---------------- scratch (device globals; total 3.55GB to stay inside the
// ±4GB R_AARCH64_ADR_PREL_PG_HI21 relocation range on the aarch64 host) ------
// Lifetime-based aliasing (launches are in-stream sequential):
//   g_khp [1GB] : kh split {hi,lo} during phases 1-4; cat[512MB] during 6-7
//   g_vhp [1GB] : vh split {hi,lo}
//   g_qh [512MB]: qh tf32-rounded
//   g_sc  [1GB] : head hosts weight-splits(48MB)+rounded-inputs(192MB) phases 0-3;
//                 whole buffer = scores/probs from phase 4 on
//   g_wop [16MB]: permuted+split Wo (needed to the end, no alias)
__device__ __align__(16) float2 g_khp[134217728];
__device__ __align__(16) float2 g_vhp[134217728];
__device__ __align__(16) float  g_qh[134217728];
__device__ __align__(16) float  g_sc[268435456];
__device__ __align__(16) float2 g_wop[2097152];

// alias offsets inside g_sc (float2 units for weights, float units for inputs)
#define WKP_OFF2 0
#define WVP_OFF2 2097152
#define WQP_OFF2 4194304
#define KA_OFF   12582912
#define VA_OFF   29360128
#define QA_OFF   46137344

// ---------------- helpers ----------------
__device__ __forceinline__ unsigned tf32_hi(float x) {
    unsigned h;
    asm("cvt.rna.tf32.f32 %0, %1;" : "=r"(h) : "f"(x));
    return h;
}
__device__ __forceinline__ float tf32_rnd(float x) {
    return __uint_as_float(tf32_hi(x));
}
__device__ __forceinline__ float2 tf32_split(float x) {
    float h = tf32_rnd(x);
    float l = tf32_rnd(x - h);
    return make_float2(h, l);
}

__device__ __forceinline__ void mma_tf32(float c[4],
                                         unsigned a0, unsigned a1, unsigned a2, unsigned a3,
                                         unsigned b0, unsigned b1) {
    asm volatile(
        "mma.sync.aligned.m16n8k8.row.col.f32.tf32.tf32.f32 "
        "{%0,%1,%2,%3},{%4,%5,%6,%7},{%8,%9},{%0,%1,%2,%3};\n"
        : "+f"(c[0]), "+f"(c[1]), "+f"(c[2]), "+f"(c[3])
        : "r"(a0), "r"(a1), "r"(a2), "r"(a3), "r"(b0), "r"(b1));
}

__device__ __forceinline__ void cpa16(uint32_t dst, const void* src) {
    asm volatile("cp.async.cg.shared.global [%0], [%1], 16;\n" :: "r"(dst), "l"(src));
}
__device__ __forceinline__ void cpa_commit() { asm volatile("cp.async.commit_group;\n" ::: "memory"); }
__device__ __forceinline__ void cpa_wait0()  { asm volatile("cp.async.wait_group 0;\n" ::: "memory"); }

// ---------------- GEMM: A pre-rounded tf32 (f32 bits), B pre-split float2{hi,lo} ---
// C[m,n] = sum_k A[m,k]*(Bhi+Blo)[k,n] via 2 mma. Zero ALU conversions in loop.
// Tile 128x64x16, 256 threads (8 warps: 4 M x 2 N), warp tile 32x32, 2-stage cp.async.
// MODE 0: projection  Y[h] = X @ W[h]^T + b[h]  (z=head; SEL 0:kh-split 1:vh-split 2:qh-rnd)
// MODE 1: scores S = qh @ kh^T                  (z=b*H+h), raw f32 out
// MODE 2: O = P @ vh (NN) -> cat (tf32-rnd)     (z=b*H+h)
// MODE 3: out = cat @ Wo'^T + bo                (z=0), raw f32 out

#define BM 128
#define BNT 64
#define BK 16
#define AROW 20          // floats: BK + 4 pad
#define BR_NT 20         // float2: BK + 4 pad  (stride 40 words == 8 mod 32 -> conflict-free LDS.64)
#define BR_NN 66         // float2: BNT + 2 pad

template<int MODE, int SEL>
__global__ __launch_bounds__(256, 2)
void gemmp(const float* __restrict__ PB, float* __restrict__ PO)
{
    constexpr long BNrows = (long)CB * CN;                 // 32768
    constexpr int KD  = (MODE == 2) ? 1024 : (MODE == 3 ? 4096 : 512);
    constexpr int LDA = (MODE == 2) ? 1024 : (MODE == 3 ? 4096 : 512);
    constexpr int LDB = (MODE == 3) ? 4096 : 512;          // float2 elems
    constexpr int LDC = (MODE == 1) ? 1024 : (MODE == 2 ? 4096 : 512);
    constexpr bool NT   = (MODE != 2);
    constexpr bool HASB = (MODE == 0 || MODE == 3);
    // EPI: 0 raw f32, 1 tf32-rounded f32, 2 split float2
    constexpr int EPI = (MODE == 0) ? ((SEL == 2) ? 1 : 2) : ((MODE == 2) ? 1 : 0);
    constexpr int ABUF  = BM * AROW;                        // floats per A stage
    constexpr int BBUF2 = NT ? (BNT * BR_NT) : (BK * BR_NN); // float2 per B stage

    const int z = blockIdx.z;
    const float*  A;
    const float2* Bp;
    const float*  bias = nullptr;
    float*  C  = nullptr;
    float2* C2 = nullptr;

    if constexpr (MODE == 0) {
        A    = g_sc + ((SEL == 0) ? KA_OFF : (SEL == 1) ? VA_OFF : QA_OFF);
        Bp   = reinterpret_cast<const float2*>(g_sc)
               + ((SEL == 0) ? WKP_OFF2 : (SEL == 1) ? WVP_OFF2 : WQP_OFF2)
               + (size_t)z * 512 * 512;
        bias = PB + (size_t)z * 512;
        if constexpr (SEL == 0)      C2 = g_khp + (size_t)z * BNrows * 512;
        else if constexpr (SEL == 1) C2 = g_vhp + (size_t)z * BNrows * 512;
        else                         C  = g_qh  + (size_t)z * BNrows * 512;
    } else if constexpr (MODE == 1) {
        const int b = z >> 3, h = z & 7;
        const size_t off = ((size_t)h * BNrows + (size_t)b * CN) * 512;
        A  = g_qh + off;
        Bp = g_khp + off;
        C  = g_sc + (size_t)z * CN * CN;
    } else if constexpr (MODE == 2) {
        const int b = z >> 3, h = z & 7;
        A  = g_sc + (size_t)z * CN * CN;
        Bp = g_vhp + ((size_t)h * BNrows + (size_t)b * CN) * 512;
        C  = reinterpret_cast<float*>(g_khp) + ((size_t)b * CN * CH + h) * 512;  // cat alias
    } else {
        A = reinterpret_cast<const float*>(g_khp);  // cat alias
        Bp = g_wop; bias = PB; C = PO;
    }

    const int m0 = blockIdx.y * BM;
    const int n0 = blockIdx.x * BNT;
    const int tid = threadIdx.x;

    __shared__ __align__(16) float  As[2 * ABUF];
    __shared__ __align__(16) float2 Bs[2 * BBUF2];

    const uint32_t as_base = (uint32_t)__cvta_generic_to_shared(&As[0]);
    const uint32_t bs_base = (uint32_t)__cvta_generic_to_shared(&Bs[0]);

    // ---- cp.async mappings ----
    // A: 128 rows x 16 k floats = 512 x 16B chunks; thread does rows a_r and a_r+64.
    const int a_r  = tid >> 2;            // 0..63
    const int a_kq = (tid & 3) * 4;       // 0,4,8,12
    const float* aSrc0 = A + (size_t)(m0 + a_r) * LDA + a_kq;
    const float* aSrc1 = A + (size_t)(m0 + a_r + 64) * LDA + a_kq;
    const uint32_t aDst0 = as_base + (uint32_t)(a_r * AROW + a_kq) * 4u;
    const uint32_t aDst1 = aDst0 + (uint32_t)(64 * AROW) * 4u;

    // B: 8KB per stage = 512 x 16B chunks (2 float2 per chunk); thread does tid, tid+256.
    const float2* bSrcA; const float2* bSrcB;
    uint32_t bDstA, bDstB;
    if constexpr (NT) {                   // tile 64 n-rows x 16 k
        const int c0 = tid, c1 = tid + 256;
        const int r0 = c0 >> 3, kq0 = (c0 & 7) * 2;
        const int r1 = c1 >> 3, kq1 = (c1 & 7) * 2;
        bSrcA = Bp + (size_t)(n0 + r0) * LDB + kq0;
        bSrcB = Bp + (size_t)(n0 + r1) * LDB + kq1;
        bDstA = bs_base + (uint32_t)(r0 * BR_NT + kq0) * 8u;
        bDstB = bs_base + (uint32_t)(r1 * BR_NT + kq1) * 8u;
    } else {                              // tile 16 k-rows x 64 n
        const int c0 = tid, c1 = tid + 256;
        const int k0r = c0 >> 5, nq0 = (c0 & 31) * 2;
        const int k1r = c1 >> 5, nq1 = (c1 & 31) * 2;
        bSrcA = Bp + (size_t)k0r * LDB + n0 + nq0;
        bSrcB = Bp + (size_t)k1r * LDB + n0 + nq1;
        bDstA = bs_base + (uint32_t)(k0r * BR_NN + nq0) * 8u;
        bDstB = bs_base + (uint32_t)(k1r * BR_NN + nq1) * 8u;
    }

    const int warp = tid >> 5, lane = tid & 31;
    const int wm = (warp & 3) * 32;
    const int wn = (warp >> 2) * 32;
    const int grp = lane >> 2, qd = lane & 3;

    float acc[2][4][4];
    #pragma unroll
    for (int i = 0; i < 2; i++)
        #pragma unroll
        for (int j = 0; j < 4; j++)
            #pragma unroll
            for (int t = 0; t < 4; t++) acc[i][j][t] = 0.f;

    // ---- prologue: tile 0 into buffer 0 ----
    cpa16(aDst0, aSrc0);
    cpa16(aDst1, aSrc1);
    cpa16(bDstA, bSrcA);
    cpa16(bDstB, bSrcB);
    cpa_commit();

    const int ktiles = KD / BK;
    for (int t = 0; t < ktiles; ++t) {
        const int cur = t & 1;
        cpa_wait0();
        __syncthreads();

        if (t + 1 < ktiles) {
            const int nxt = cur ^ 1;
            const size_t koff = (size_t)(t + 1) * BK;
            cpa16(aDst0 + (uint32_t)(nxt * ABUF) * 4u, aSrc0 + koff);
            cpa16(aDst1 + (uint32_t)(nxt * ABUF) * 4u, aSrc1 + koff);
            if constexpr (NT) {
                cpa16(bDstA + (uint32_t)(nxt * BBUF2) * 8u, bSrcA + koff);
                cpa16(bDstB + (uint32_t)(nxt * BBUF2) * 8u, bSrcB + koff);
            } else {
                cpa16(bDstA + (uint32_t)(nxt * BBUF2) * 8u, bSrcA + koff * LDB);
                cpa16(bDstB + (uint32_t)(nxt * BBUF2) * 8u, bSrcB + koff * LDB);
            }
            cpa_commit();
        }

        const float*  as = &As[cur * ABUF];
        const float2* bs = &Bs[cur * BBUF2];

        #pragma unroll
        for (int ks = 0; ks < 2; ++ks) {
            const int k0 = ks * 8 + qd;
            const int k1 = k0 + 4;

            // A fragments: pre-rounded tf32 -> raw bit passthrough
            unsigned ah[2][4];
            #pragma unroll
            for (int fm = 0; fm < 2; fm++) {
                const int r0 = wm + fm * 16 + grp;
                ah[fm][0] = __float_as_uint(as[r0 * AROW + k0]);
                ah[fm][1] = __float_as_uint(as[(r0 + 8) * AROW + k0]);
                ah[fm][2] = __float_as_uint(as[r0 * AROW + k1]);
                ah[fm][3] = __float_as_uint(as[(r0 + 8) * AROW + k1]);
            }
            // B fragments: pre-split {hi,lo} -> one LDS.64 each
            unsigned bh[4][2], bl[4][2];
            #pragma unroll
            for (int fn = 0; fn < 4; fn++) {
                const int c = wn + fn * 8 + grp;
                float2 w0, w1;
                if constexpr (NT) { w0 = bs[c * BR_NT + k0]; w1 = bs[c * BR_NT + k1]; }
                else              { w0 = bs[k0 * BR_NN + c]; w1 = bs[k1 * BR_NN + c]; }
                bh[fn][0] = __float_as_uint(w0.x); bl[fn][0] = __float_as_uint(w0.y);
                bh[fn][1] = __float_as_uint(w1.x); bl[fn][1] = __float_as_uint(w1.y);
            }

            #pragma unroll
            for (int fm = 0; fm < 2; fm++) {
                #pragma unroll
                for (int fn = 0; fn < 4; fn++) {
                    mma_tf32(acc[fm][fn], ah[fm][0], ah[fm][1], ah[fm][2], ah[fm][3],
                             bh[fn][0], bh[fn][1]);                       // a*bhi
                    mma_tf32(acc[fm][fn], ah[fm][0], ah[fm][1], ah[fm][2], ah[fm][3],
                             bl[fn][0], bl[fn][1]);                       // a*blo
                }
            }
        }
    }

    // ---- epilogue ----
    #pragma unroll
    for (int fm = 0; fm < 2; fm++) {
        const int r = m0 + wm + fm * 16 + grp;
        #pragma unroll
        for (int fn = 0; fn < 4; fn++) {
            const int cc = n0 + wn + fn * 8 + qd * 2;
            float v[4] = { acc[fm][fn][0], acc[fm][fn][1], acc[fm][fn][2], acc[fm][fn][3] };
            if constexpr (HASB) {
                const float2 bb = *(const float2*)(bias + cc);
                v[0] += bb.x; v[1] += bb.y; v[2] += bb.x; v[3] += bb.y;
            }
            if constexpr (EPI == 0) {
                *(float2*)(C + (size_t)r * LDC + cc)       = make_float2(v[0], v[1]);
                *(float2*)(C + (size_t)(r + 8) * LDC + cc) = make_float2(v[2], v[3]);
            } else if constexpr (EPI == 1) {
                *(float2*)(C + (size_t)r * LDC + cc)       = make_float2(tf32_rnd(v[0]), tf32_rnd(v[1]));
                *(float2*)(C + (size_t)(r + 8) * LDC + cc) = make_float2(tf32_rnd(v[2]), tf32_rnd(v[3]));
            } else {
                float2 s0 = tf32_split(v[0]), s1 = tf32_split(v[1]);
                float2 s2 = tf32_split(v[2]), s3 = tf32_split(v[3]);
                *(float4*)(C2 + (size_t)r * LDC + cc)       = make_float4(s0.x, s0.y, s1.x, s1.y);
                *(float4*)(C2 + (size_t)(r + 8) * LDC + cc) = make_float4(s2.x, s2.y, s3.x, s3.y);
            }
        }
    }
}

// ---------------- softmax (scale folded in); stores tf32-rounded probs ----------------
__global__ void softmax_k()
{
    const size_t row = blockIdx.x;                    // B*H*N = 262144 rows
    float* p = g_sc + row * 1024;
    const int tid = threadIdx.x;                      // 256 threads, 4 elems each
    float4 v = reinterpret_cast<float4*>(p)[tid];

    float m = fmaxf(fmaxf(v.x, v.y), fmaxf(v.z, v.w));
    #pragma unroll
    for (int o = 16; o; o >>= 1) m = fmaxf(m, __shfl_xor_sync(0xffffffffu, m, o));
    __shared__ float sm[8];
    if ((tid & 31) == 0) sm[tid >> 5] = m;
    __syncthreads();
    const float mm = fmaxf(fmaxf(fmaxf(sm[0], sm[1]), fmaxf(sm[2], sm[3])),
                           fmaxf(fmaxf(sm[4], sm[5]), fmaxf(sm[6], sm[7])));

    const float INV_TAU = 0.044194173824159216f;      // 1/sqrt(512)
    v.x = __expf((v.x - mm) * INV_TAU);
    v.y = __expf((v.y - mm) * INV_TAU);
    v.z = __expf((v.z - mm) * INV_TAU);
    v.w = __expf((v.w - mm) * INV_TAU);

    float s = v.x + v.y + v.z + v.w;
    #pragma unroll
    for (int o = 16; o; o >>= 1) s += __shfl_xor_sync(0xffffffffu, s, o);
    __shared__ float ss[8];
    if ((tid & 31) == 0) ss[tid >> 5] = s;
    __syncthreads();
    const float tot = ss[0] + ss[1] + ss[2] + ss[3] + ss[4] + ss[5] + ss[6] + ss[7];

    const float inv = 1.0f / tot;
    v.x = tf32_rnd(v.x * inv);
    v.y = tf32_rnd(v.y * inv);
    v.z = tf32_rnd(v.z * inv);
    v.w = tf32_rnd(v.w * inv);
    reinterpret_cast<float4*>(p)[tid] = v;
}

// ---------------- prep kernels (write into g_sc head aliases) ----------------
__global__ void prep_in(const float* __restrict__ k, const float* __restrict__ v,
                        const float* __restrict__ q)
{
    const int i = blockIdx.x * blockDim.x + threadIdx.x;   // 16777216
    if (i >= 16777216) return;
    g_sc[KA_OFF + i] = tf32_rnd(k[i]);
    g_sc[VA_OFF + i] = tf32_rnd(v[i]);
    g_sc[QA_OFF + i] = tf32_rnd(q[i]);
}

__global__ void prep_w(const float* __restrict__ Wk, const float* __restrict__ Wv,
                       const float* __restrict__ Wq)
{
    const int i = blockIdx.x * blockDim.x + threadIdx.x;   // 2097152
    if (i >= 2097152) return;
    float2* base = reinterpret_cast<float2*>(g_sc);
    base[WKP_OFF2 + i] = tf32_split(Wk[i]);
    base[WVP_OFF2 + i] = tf32_split(Wv[i]);
    base[WQP_OFF2 + i] = tf32_split(Wq[i]);
}

__global__ void prep_wo(const float* __restrict__ Wo)
{
    const int i = blockIdx.x * blockDim.x + threadIdx.x;   // 2097152
    if (i >= 2097152) return;
    const int e2 = i >> 12;
    const int c  = i & 4095;
    const int h  = c >> 9;
    const int d  = c & 511;
    g_wop[i] = tf32_split(Wo[(e2 << 12) + d * 8 + h]);
}

// ---------------- launch ----------------
extern "C" void kernel_launch(void* const* d_in, const int* in_sizes, int n_in,
                              void* d_out, int out_size)
{
    (void)in_sizes; (void)n_in; (void)out_size;
    const float* k  = (const float*)d_in[0];
    const float* v  = (const float*)d_in[1];
    const float* q  = (const float*)d_in[2];
    const float* Wk = (const float*)d_in[3];
    const float* bk = (const float*)d_in[4];
    const float* Wv = (const float*)d_in[5];
    const float* bv = (const float*)d_in[6];
    const float* Wq = (const float*)d_in[7];
    const float* bq = (const float*)d_in[8];
    const float* Wo = (const float*)d_in[9];
    const float* bo = (const float*)d_in[10];
    float* out = (float*)d_out;

    const dim3 blk(256);

    prep_in<<<65536, 256>>>(k, v, q);
    prep_w<<<8192, 256>>>(Wk, Wv, Wq);
    prep_wo<<<8192, 256>>>(Wo);

    // projections: grid (512/64=8, 32768/128=256, H=8)
    gemmp<0, 0><<<dim3(8, 256, 8), blk>>>(bk, nullptr);
    gemmp<0, 1><<<dim3(8, 256, 8), blk>>>(bv, nullptr);
    gemmp<0, 2><<<dim3(8, 256, 8), blk>>>(bq, nullptr);

    // scores: grid (1024/64=16, 1024/128=8, B*H=256)
    gemmp<1, 0><<<dim3(16, 8, 256), blk>>>(nullptr, nullptr);

    softmax_k<<<262144, 256>>>();

    // PV: grid (512/64=8, 1024/128=8, 256)
    gemmp<2, 0><<<dim3(8, 8, 256), blk>>>(nullptr, nullptr);

    // output projection: grid (512/64=8, 32768/128=256, 1)
    gemmp<3, 0><<<dim3(8, 256, 1), blk>>>(bo, out);
}

// round 16
// speedup vs baseline: 1.0863x; 1.0863x over previous
#include <cuda_runtime.h>
#include <cstdint>
#include <cstddef>

// Problem dims: B=32 N=1024 D=512 H=8 ; BN = 32768
#define CB 32
#define CN 1024
#define CD 512
#define CH 8

// ---------------- scratch (device globals; total 3.55GB to stay inside the
// ±4GB R_AARCH64_ADR_PREL_PG_HI21 relocation range on the aarch64 host) ------
// Lifetime-based aliasing (launches are in-stream sequential):
//   g_khp [1GB] : kh split {hi,lo} during phases 1-4; cat[512MB] during 6-7
//   g_vhp [1GB] : vh split {hi,lo}
//   g_qh [512MB]: qh tf32-rounded
//   g_sc  [1GB] : head hosts weight-splits(48MB)+rounded-inputs(192MB) phases 0-3;
//                 whole buffer = scores/probs from phase 4 on
//   g_wop [16MB]: permuted+split Wo (needed to the end, no alias)
__device__ __align__(16) float2 g_khp[134217728];
__device__ __align__(16) float2 g_vhp[134217728];
__device__ __align__(16) float  g_qh[134217728];
__device__ __align__(16) float  g_sc[268435456];
__device__ __align__(16) float2 g_wop[2097152];

// alias offsets inside g_sc (float2 units for weights, float units for inputs)
#define WKP_OFF2 0
#define WVP_OFF2 2097152
#define WQP_OFF2 4194304
#define KA_OFF   12582912
#define VA_OFF   29360128
#define QA_OFF   46137344

// ---------------- helpers ----------------
__device__ __forceinline__ unsigned tf32_hi(float x) {
    unsigned h;
    asm("cvt.rna.tf32.f32 %0, %1;" : "=r"(h) : "f"(x));
    return h;
}
__device__ __forceinline__ float tf32_rnd(float x) {
    return __uint_as_float(tf32_hi(x));
}
__device__ __forceinline__ float2 tf32_split(float x) {
    float h = tf32_rnd(x);
    float l = tf32_rnd(x - h);
    return make_float2(h, l);
}

__device__ __forceinline__ void mma_tf32(float c[4],
                                         unsigned a0, unsigned a1, unsigned a2, unsigned a3,
                                         unsigned b0, unsigned b1) {
    asm volatile(
        "mma.sync.aligned.m16n8k8.row.col.f32.tf32.tf32.f32 "
        "{%0,%1,%2,%3},{%4,%5,%6,%7},{%8,%9},{%0,%1,%2,%3};\n"
        : "+f"(c[0]), "+f"(c[1]), "+f"(c[2]), "+f"(c[3])
        : "r"(a0), "r"(a1), "r"(a2), "r"(a3), "r"(b0), "r"(b1));
}

__device__ __forceinline__ void cpa16(uint32_t dst, const void* src) {
    asm volatile("cp.async.cg.shared.global [%0], [%1], 16;\n" :: "r"(dst), "l"(src));
}
__device__ __forceinline__ void cpa_commit() { asm volatile("cp.async.commit_group;\n" ::: "memory"); }
__device__ __forceinline__ void cpa_wait0()  { asm volatile("cp.async.wait_group 0;\n" ::: "memory"); }

// ---------------- GEMM: A pre-rounded tf32 (f32 bits), B pre-split float2{hi,lo} ---
// C[m,n] = sum_k A[m,k]*(Bhi+Blo)[k,n] via 2 mma. Zero ALU conversions in loop.
// Tile 128x64x16, 256 threads (8 warps: 4 M x 2 N), warp tile 32x32, 2-stage cp.async.
// Occupancy experiment: 3 blocks/SM (24 warps) to discriminate latency-bound (H1)
// vs legacy-HMMA pipe ceiling (H2).
// MODE 0: projection  Y[h] = X @ W[h]^T + b[h]  (z=head; SEL 0:kh-split 1:vh-split 2:qh-rnd)
// MODE 1: scores S = qh @ kh^T                  (z=b*H+h), raw f32 out
// MODE 2: O = P @ vh (NN) -> cat (tf32-rnd)     (z=b*H+h)
// MODE 3: out = cat @ Wo'^T + bo                (z=0), raw f32 out

#define BM 128
#define BNT 64
#define BK 16
#define AROW 20          // floats: BK + 4 pad
#define BR_NT 20         // float2: BK + 4 pad  (stride 40 words == 8 mod 32 -> conflict-free LDS.64)
#define BR_NN 66         // float2: BNT + 2 pad

template<int MODE, int SEL>
__global__ __launch_bounds__(256, 3)
void gemmp(const float* __restrict__ PB, float* __restrict__ PO)
{
    constexpr long BNrows = (long)CB * CN;                 // 32768
    constexpr int KD  = (MODE == 2) ? 1024 : (MODE == 3 ? 4096 : 512);
    constexpr int LDA = (MODE == 2) ? 1024 : (MODE == 3 ? 4096 : 512);
    constexpr int LDB = (MODE == 3) ? 4096 : 512;          // float2 elems
    constexpr int LDC = (MODE == 1) ? 1024 : (MODE == 2 ? 4096 : 512);
    constexpr bool NT   = (MODE != 2);
    constexpr bool HASB = (MODE == 0 || MODE == 3);
    // EPI: 0 raw f32, 1 tf32-rounded f32, 2 split float2
    constexpr int EPI = (MODE == 0) ? ((SEL == 2) ? 1 : 2) : ((MODE == 2) ? 1 : 0);
    constexpr int ABUF  = BM * AROW;                        // floats per A stage
    constexpr int BBUF2 = NT ? (BNT * BR_NT) : (BK * BR_NN); // float2 per B stage

    const int z = blockIdx.z;
    const float*  A;
    const float2* Bp;
    const float*  bias = nullptr;
    float*  C  = nullptr;
    float2* C2 = nullptr;

    if constexpr (MODE == 0) {
        A    = g_sc + ((SEL == 0) ? KA_OFF : (SEL == 1) ? VA_OFF : QA_OFF);
        Bp   = reinterpret_cast<const float2*>(g_sc)
               + ((SEL == 0) ? WKP_OFF2 : (SEL == 1) ? WVP_OFF2 : WQP_OFF2)
               + (size_t)z * 512 * 512;
        bias = PB + (size_t)z * 512;
        if constexpr (SEL == 0)      C2 = g_khp + (size_t)z * BNrows * 512;
        else if constexpr (SEL == 1) C2 = g_vhp + (size_t)z * BNrows * 512;
        else                         C  = g_qh  + (size_t)z * BNrows * 512;
    } else if constexpr (MODE == 1) {
        const int b = z >> 3, h = z & 7;
        const size_t off = ((size_t)h * BNrows + (size_t)b * CN) * 512;
        A  = g_qh + off;
        Bp = g_khp + off;
        C  = g_sc + (size_t)z * CN * CN;
    } else if constexpr (MODE == 2) {
        const int b = z >> 3, h = z & 7;
        A  = g_sc + (size_t)z * CN * CN;
        Bp = g_vhp + ((size_t)h * BNrows + (size_t)b * CN) * 512;
        C  = reinterpret_cast<float*>(g_khp) + ((size_t)b * CN * CH + h) * 512;  // cat alias
    } else {
        A = reinterpret_cast<const float*>(g_khp);  // cat alias
        Bp = g_wop; bias = PB; C = PO;
    }

    const int m0 = blockIdx.y * BM;
    const int n0 = blockIdx.x * BNT;
    const int tid = threadIdx.x;

    __shared__ __align__(16) float  As[2 * ABUF];
    __shared__ __align__(16) float2 Bs[2 * BBUF2];

    const uint32_t as_base = (uint32_t)__cvta_generic_to_shared(&As[0]);
    const uint32_t bs_base = (uint32_t)__cvta_generic_to_shared(&Bs[0]);

    // ---- cp.async mappings ----
    // A: 128 rows x 16 k floats = 512 x 16B chunks; thread does rows a_r and a_r+64.
    const int a_r  = tid >> 2;            // 0..63
    const int a_kq = (tid & 3) * 4;       // 0,4,8,12
    const float* aSrc0 = A + (size_t)(m0 + a_r) * LDA + a_kq;
    const float* aSrc1 = A + (size_t)(m0 + a_r + 64) * LDA + a_kq;
    const uint32_t aDst0 = as_base + (uint32_t)(a_r * AROW + a_kq) * 4u;
    const uint32_t aDst1 = aDst0 + (uint32_t)(64 * AROW) * 4u;

    // B: 8KB per stage = 512 x 16B chunks (2 float2 per chunk); thread does tid, tid+256.
    const float2* bSrcA; const float2* bSrcB;
    uint32_t bDstA, bDstB;
    if constexpr (NT) {                   // tile 64 n-rows x 16 k
        const int c0 = tid, c1 = tid + 256;
        const int r0 = c0 >> 3, kq0 = (c0 & 7) * 2;
        const int r1 = c1 >> 3, kq1 = (c1 & 7) * 2;
        bSrcA = Bp + (size_t)(n0 + r0) * LDB + kq0;
        bSrcB = Bp + (size_t)(n0 + r1) * LDB + kq1;
        bDstA = bs_base + (uint32_t)(r0 * BR_NT + kq0) * 8u;
        bDstB = bs_base + (uint32_t)(r1 * BR_NT + kq1) * 8u;
    } else {                              // tile 16 k-rows x 64 n
        const int c0 = tid, c1 = tid + 256;
        const int k0r = c0 >> 5, nq0 = (c0 & 31) * 2;
        const int k1r = c1 >> 5, nq1 = (c1 & 31) * 2;
        bSrcA = Bp + (size_t)k0r * LDB + n0 + nq0;
        bSrcB = Bp + (size_t)k1r * LDB + n0 + nq1;
        bDstA = bs_base + (uint32_t)(k0r * BR_NN + nq0) * 8u;
        bDstB = bs_base + (uint32_t)(k1r * BR_NN + nq1) * 8u;
    }

    const int warp = tid >> 5, lane = tid & 31;
    const int wm = (warp & 3) * 32;
    const int wn = (warp >> 2) * 32;
    const int grp = lane >> 2, qd = lane & 3;

    float acc[2][4][4];
    #pragma unroll
    for (int i = 0; i < 2; i++)
        #pragma unroll
        for (int j = 0; j < 4; j++)
            #pragma unroll
            for (int t = 0; t < 4; t++) acc[i][j][t] = 0.f;

    // ---- prologue: tile 0 into buffer 0 ----
    cpa16(aDst0, aSrc0);
    cpa16(aDst1, aSrc1);
    cpa16(bDstA, bSrcA);
    cpa16(bDstB, bSrcB);
    cpa_commit();

    const int ktiles = KD / BK;
    for (int t = 0; t < ktiles; ++t) {
        const int cur = t & 1;
        cpa_wait0();
        __syncthreads();

        if (t + 1 < ktiles) {
            const int nxt = cur ^ 1;
            const size_t koff = (size_t)(t + 1) * BK;
            cpa16(aDst0 + (uint32_t)(nxt * ABUF) * 4u, aSrc0 + koff);
            cpa16(aDst1 + (uint32_t)(nxt * ABUF) * 4u, aSrc1 + koff);
            if constexpr (NT) {
                cpa16(bDstA + (uint32_t)(nxt * BBUF2) * 8u, bSrcA + koff);
                cpa16(bDstB + (uint32_t)(nxt * BBUF2) * 8u, bSrcB + koff);
            } else {
                cpa16(bDstA + (uint32_t)(nxt * BBUF2) * 8u, bSrcA + koff * LDB);
                cpa16(bDstB + (uint32_t)(nxt * BBUF2) * 8u, bSrcB + koff * LDB);
            }
            cpa_commit();
        }

        const float*  as = &As[cur * ABUF];
        const float2* bs = &Bs[cur * BBUF2];

        #pragma unroll
        for (int ks = 0; ks < 2; ++ks) {
            const int k0 = ks * 8 + qd;
            const int k1 = k0 + 4;

            // A fragments: pre-rounded tf32 -> raw bit passthrough
            unsigned ah[2][4];
            #pragma unroll
            for (int fm = 0; fm < 2; fm++) {
                const int r0 = wm + fm * 16 + grp;
                ah[fm][0] = __float_as_uint(as[r0 * AROW + k0]);
                ah[fm][1] = __float_as_uint(as[(r0 + 8) * AROW + k0]);
                ah[fm][2] = __float_as_uint(as[r0 * AROW + k1]);
                ah[fm][3] = __float_as_uint(as[(r0 + 8) * AROW + k1]);
            }
            // B fragments: pre-split {hi,lo} -> one LDS.64 each
            unsigned bh[4][2], bl[4][2];
            #pragma unroll
            for (int fn = 0; fn < 4; fn++) {
                const int c = wn + fn * 8 + grp;
                float2 w0, w1;
                if constexpr (NT) { w0 = bs[c * BR_NT + k0]; w1 = bs[c * BR_NT + k1]; }
                else              { w0 = bs[k0 * BR_NN + c]; w1 = bs[k1 * BR_NN + c]; }
                bh[fn][0] = __float_as_uint(w0.x); bl[fn][0] = __float_as_uint(w0.y);
                bh[fn][1] = __float_as_uint(w1.x); bl[fn][1] = __float_as_uint(w1.y);
            }

            #pragma unroll
            for (int fm = 0; fm < 2; fm++) {
                #pragma unroll
                for (int fn = 0; fn < 4; fn++) {
                    mma_tf32(acc[fm][fn], ah[fm][0], ah[fm][1], ah[fm][2], ah[fm][3],
                             bh[fn][0], bh[fn][1]);                       // a*bhi
                    mma_tf32(acc[fm][fn], ah[fm][0], ah[fm][1], ah[fm][2], ah[fm][3],
                             bl[fn][0], bl[fn][1]);                       // a*blo
                }
            }
        }
    }

    // ---- epilogue ----
    #pragma unroll
    for (int fm = 0; fm < 2; fm++) {
        const int r = m0 + wm + fm * 16 + grp;
        #pragma unroll
        for (int fn = 0; fn < 4; fn++) {
            const int cc = n0 + wn + fn * 8 + qd * 2;
            float v[4] = { acc[fm][fn][0], acc[fm][fn][1], acc[fm][fn][2], acc[fm][fn][3] };
            if constexpr (HASB) {
                const float2 bb = *(const float2*)(bias + cc);
                v[0] += bb.x; v[1] += bb.y; v[2] += bb.x; v[3] += bb.y;
            }
            if constexpr (EPI == 0) {
                *(float2*)(C + (size_t)r * LDC + cc)       = make_float2(v[0], v[1]);
                *(float2*)(C + (size_t)(r + 8) * LDC + cc) = make_float2(v[2], v[3]);
            } else if constexpr (EPI == 1) {
                *(float2*)(C + (size_t)r * LDC + cc)       = make_float2(tf32_rnd(v[0]), tf32_rnd(v[1]));
                *(float2*)(C + (size_t)(r + 8) * LDC + cc) = make_float2(tf32_rnd(v[2]), tf32_rnd(v[3]));
            } else {
                float2 s0 = tf32_split(v[0]), s1 = tf32_split(v[1]);
                float2 s2 = tf32_split(v[2]), s3 = tf32_split(v[3]);
                *(float4*)(C2 + (size_t)r * LDC + cc)       = make_float4(s0.x, s0.y, s1.x, s1.y);
                *(float4*)(C2 + (size_t)(r + 8) * LDC + cc) = make_float4(s2.x, s2.y, s3.x, s3.y);
            }
        }
    }
}

// ---------------- softmax (scale folded in); stores tf32-rounded probs ----------------
__global__ void softmax_k()
{
    const size_t row = blockIdx.x;                    // B*H*N = 262144 rows
    float* p = g_sc + row * 1024;
    const int tid = threadIdx.x;                      // 256 threads, 4 elems each
    float4 v = reinterpret_cast<float4*>(p)[tid];

    float m = fmaxf(fmaxf(v.x, v.y), fmaxf(v.z, v.w));
    #pragma unroll
    for (int o = 16; o; o >>= 1) m = fmaxf(m, __shfl_xor_sync(0xffffffffu, m, o));
    __shared__ float sm[8];
    if ((tid & 31) == 0) sm[tid >> 5] = m;
    __syncthreads();
    const float mm = fmaxf(fmaxf(fmaxf(sm[0], sm[1]), fmaxf(sm[2], sm[3])),
                           fmaxf(fmaxf(sm[4], sm[5]), fmaxf(sm[6], sm[7])));

    const float INV_TAU = 0.044194173824159216f;      // 1/sqrt(512)
    v.x = __expf((v.x - mm) * INV_TAU);
    v.y = __expf((v.y - mm) * INV_TAU);
    v.z = __expf((v.z - mm) * INV_TAU);
    v.w = __expf((v.w - mm) * INV_TAU);

    float s = v.x + v.y + v.z + v.w;
    #pragma unroll
    for (int o = 16; o; o >>= 1) s += __shfl_xor_sync(0xffffffffu, s, o);
    __shared__ float ss[8];
    if ((tid & 31) == 0) ss[tid >> 5] = s;
    __syncthreads();
    const float tot = ss[0] + ss[1] + ss[2] + ss[3] + ss[4] + ss[5] + ss[6] + ss[7];

    const float inv = 1.0f / tot;
    v.x = tf32_rnd(v.x * inv);
    v.y = tf32_rnd(v.y * inv);
    v.z = tf32_rnd(v.z * inv);
    v.w = tf32_rnd(v.w * inv);
    reinterpret_cast<float4*>(p)[tid] = v;
}

// ---------------- prep kernels (write into g_sc head aliases) ----------------
__global__ void prep_in(const float* __restrict__ k, const float* __restrict__ v,
                        const float* __restrict__ q)
{
    const int i = blockIdx.x * blockDim.x + threadIdx.x;   // 16777216
    if (i >= 16777216) return;
    g_sc[KA_OFF + i] = tf32_rnd(k[i]);
    g_sc[VA_OFF + i] = tf32_rnd(v[i]);
    g_sc[QA_OFF + i] = tf32_rnd(q[i]);
}

__global__ void prep_w(const float* __restrict__ Wk, const float* __restrict__ Wv,
                       const float* __restrict__ Wq)
{
    const int i = blockIdx.x * blockDim.x + threadIdx.x;   // 2097152
    if (i >= 2097152) return;
    float2* base = reinterpret_cast<float2*>(g_sc);
    base[WKP_OFF2 + i] = tf32_split(Wk[i]);
    base[WVP_OFF2 + i] = tf32_split(Wv[i]);
    base[WQP_OFF2 + i] = tf32_split(Wq[i]);
}

__global__ void prep_wo(const float* __restrict__ Wo)
{
    const int i = blockIdx.x * blockDim.x + threadIdx.x;   // 2097152
    if (i >= 2097152) return;
    const int e2 = i >> 12;
    const int c  = i & 4095;
    const int h  = c >> 9;
    const int d  = c & 511;
    g_wop[i] = tf32_split(Wo[(e2 << 12) + d * 8 + h]);
}

// ---------------- launch ----------------
extern "C" void kernel_launch(void* const* d_in, const int* in_sizes, int n_in,
                              void* d_out, int out_size)
{
    (void)in_sizes; (void)n_in; (void)out_size;
    const float* k  = (const float*)d_in[0];
    const float* v  = (const float*)d_in[1];
    const float* q  = (const float*)d_in[2];
    const float* Wk = (const float*)d_in[3];
    const float* bk = (const float*)d_in[4];
    const float* Wv = (const float*)d_in[5];
    const float* bv = (const float*)d_in[6];
    const float* Wq = (const float*)d_in[7];
    const float* bq = (const float*)d_in[8];
    const float* Wo = (const float*)d_in[9];
    const float* bo = (const float*)d_in[10];
    float* out = (float*)d_out;

    const dim3 blk(256);

    prep_in<<<65536, 256>>>(k, v, q);
    prep_w<<<8192, 256>>>(Wk, Wv, Wq);
    prep_wo<<<8192, 256>>>(Wo);

    // projections: grid (512/64=8, 32768/128=256, H=8)
    gemmp<0, 0><<<dim3(8, 256, 8), blk>>>(bk, nullptr);
    gemmp<0, 1><<<dim3(8, 256, 8), blk>>>(bv, nullptr);
    gemmp<0, 2><<<dim3(8, 256, 8), blk>>>(bq, nullptr);

    // scores: grid (1024/64=16, 1024/128=8, B*H=256)
    gemmp<1, 0><<<dim3(16, 8, 256), blk>>>(nullptr, nullptr);

    softmax_k<<<262144, 256>>>();

    // PV: grid (512/64=8, 1024/128=8, 256)
    gemmp<2, 0><<<dim3(8, 8, 256), blk>>>(nullptr, nullptr);

    // output projection: grid (512/64=8, 32768/128=256, 1)
    gemmp<3, 0><<<dim3(8, 256, 1), blk>>>(bo, out);
}